// round 1
// baseline (speedup 1.0000x reference)
#include <cuda_runtime.h>
#include <math.h>

#define Bq 4
#define Tq 4096
#define Cq 1024
#define Hq 64

// Scratch: q,k transposed to [B,H,T] for coalesced attention tile loads; v natural [B,T,H].
__device__ float g_qT[Bq * Hq * Tq];
__device__ float g_kT[Bq * Hq * Tq];
__device__ float g_v[Bq * Tq * Hq];

// ---------------------------------------------------------------------------
// Projection: out[row, 0:192] = x[row, :] @ [Wq | Wk | Wv]
// BM=64 rows per block, all N=192 columns, K chunked by 32.
// 256 threads, 4x12 register micro-tile per thread.
// ---------------------------------------------------------------------------
#define PJ_BM 64
#define PJ_KC 32
#define PJ_N 192

__global__ __launch_bounds__(256) void proj_kernel(const float* __restrict__ x,
                                                   const float* __restrict__ Wq,
                                                   const float* __restrict__ Wk,
                                                   const float* __restrict__ Wv) {
    __shared__ float xsT[PJ_KC][PJ_BM];  // [k][m]
    __shared__ float Ws[PJ_KC][PJ_N];    // [k][n]

    const int tid = threadIdx.x;
    const int tr = tid >> 4;       // 0..15
    const int tc = tid & 15;       // 0..15
    const int m0 = tr * 4;
    const int n0 = tc * 12;
    const int row0 = blockIdx.x * PJ_BM;

    float acc[4][12];
#pragma unroll
    for (int u = 0; u < 4; u++)
#pragma unroll
        for (int v = 0; v < 12; v++) acc[u][v] = 0.f;

    for (int kc = 0; kc < Cq; kc += PJ_KC) {
        // Load x tile (64 rows x 32 k) transposed into smem
        for (int idx = tid; idx < (PJ_BM * PJ_KC / 4); idx += 256) {
            int m = idx >> 3;
            int kq = idx & 7;
            float4 xv = *(const float4*)&x[(row0 + m) * Cq + kc + kq * 4];
            xsT[kq * 4 + 0][m] = xv.x;
            xsT[kq * 4 + 1][m] = xv.y;
            xsT[kq * 4 + 2][m] = xv.z;
            xsT[kq * 4 + 3][m] = xv.w;
        }
        // Load W tile (32 k x 192 n)
        for (int idx = tid; idx < PJ_KC * PJ_N; idx += 256) {
            int k = idx / PJ_N;
            int n = idx % PJ_N;
            const float* W = (n < 64) ? Wq : ((n < 128) ? Wk : Wv);
            Ws[k][n] = W[(kc + k) * Hq + (n & 63)];
        }
        __syncthreads();

#pragma unroll 4
        for (int k = 0; k < PJ_KC; k++) {
            float4 a4 = *(const float4*)&xsT[k][m0];
            float av[4] = {a4.x, a4.y, a4.z, a4.w};
            float4 b0 = *(const float4*)&Ws[k][n0];
            float4 b1 = *(const float4*)&Ws[k][n0 + 4];
            float4 b2 = *(const float4*)&Ws[k][n0 + 8];
            float bv[12] = {b0.x, b0.y, b0.z, b0.w, b1.x, b1.y,
                            b1.z, b1.w, b2.x, b2.y, b2.z, b2.w};
#pragma unroll
            for (int u = 0; u < 4; u++)
#pragma unroll
                for (int v = 0; v < 12; v++) acc[u][v] = fmaf(av[u], bv[v], acc[u][v]);
        }
        __syncthreads();
    }

    // Scatter results: q,k transposed [B,H,T]; v natural [B,T,H]
#pragma unroll
    for (int u = 0; u < 4; u++) {
        int row = row0 + m0 + u;
        int b = row / Tq;
        int t = row % Tq;
#pragma unroll
        for (int v = 0; v < 12; v++) {
            int n = n0 + v;
            float val = acc[u][v];
            if (n < 64) {
                g_qT[(b * Hq + n) * Tq + t] = val;
            } else if (n < 128) {
                g_kT[(b * Hq + (n - 64)) * Tq + t] = val;
            } else {
                g_v[row * Hq + (n - 128)] = val;
            }
        }
    }
}

// ---------------------------------------------------------------------------
// Flash attention: per (batch, 64-query tile) block, stream key tiles of 64.
// 256 threads; 4x4 micro-tiles for both GEMMs; online softmax in smem.
// ---------------------------------------------------------------------------
#define AT_BM 64
#define AT_BN 64
#define ATT_SCALE 0.03125f  // 1/sqrt(1024)

#define SMEM_FLOATS (3 * 4096 + 64 * 65 + 3 * 64)

__global__ __launch_bounds__(256) void attn_kernel(float* __restrict__ out) {
    extern __shared__ float sm[];
    float* QsT = sm;             // [h][m]  64x64
    float* KsT = QsT + 4096;     // [h][j]  64x64
    float* Vs = KsT + 4096;      // [j][h]  64x64
    float* Ss = Vs + 4096;       // [i][j]  64x65 (pad)
    float* m_s = Ss + 64 * 65;   // 64
    float* l_s = m_s + 64;       // 64
    float* rs_s = l_s + 64;      // 64

    const int tid = threadIdx.x;
    const int tr = tid >> 4;  // 0..15
    const int tc = tid & 15;  // 0..15
    const int i0 = tr * 4;
    const int j0 = tc * 4;
    const int h0 = tc * 4;
    const int b = blockIdx.y;
    const int it = (gridDim.x - 1) - blockIdx.x;  // big tiles first
    const int qm0 = it * AT_BM;

    // Load Q tile (already transposed in gmem: [b][h][t])
    for (int idx = tid; idx < 64 * 16; idx += 256) {
        int h = idx >> 4;
        int mq = idx & 15;
        *(float4*)&QsT[h * 64 + mq * 4] =
            *(const float4*)&g_qT[(b * Hq + h) * Tq + qm0 + mq * 4];
    }
    if (tid < 64) {
        m_s[tid] = -1e30f;
        l_s[tid] = 0.f;
    }

    float o[4][4];
#pragma unroll
    for (int u = 0; u < 4; u++)
#pragma unroll
        for (int v = 0; v < 4; v++) o[u][v] = 0.f;

    for (int kt = 0; kt <= it; kt++) {
        const int kn0 = kt * AT_BN;
        __syncthreads();  // prior PV done before overwriting K/V tiles
        for (int idx = tid; idx < 64 * 16; idx += 256) {
            int h = idx >> 4;
            int jq = idx & 15;
            *(float4*)&KsT[h * 64 + jq * 4] =
                *(const float4*)&g_kT[(b * Hq + h) * Tq + kn0 + jq * 4];
        }
        for (int idx = tid; idx < 64 * 16; idx += 256) {
            int j = idx >> 4;
            int hq = idx & 15;
            *(float4*)&Vs[j * 64 + hq * 4] =
                *(const float4*)&g_v[(b * Tq + kn0 + j) * Hq + hq * 4];
        }
        __syncthreads();

        // S = Q @ K^T (4x4 per thread)
        float s[4][4];
#pragma unroll
        for (int u = 0; u < 4; u++)
#pragma unroll
            for (int v = 0; v < 4; v++) s[u][v] = 0.f;
#pragma unroll 16
        for (int h = 0; h < 64; h++) {
            float4 a4 = *(const float4*)&QsT[h * 64 + i0];
            float4 b4 = *(const float4*)&KsT[h * 64 + j0];
            float av[4] = {a4.x, a4.y, a4.z, a4.w};
            float bv[4] = {b4.x, b4.y, b4.z, b4.w};
#pragma unroll
            for (int u = 0; u < 4; u++)
#pragma unroll
                for (int v = 0; v < 4; v++) s[u][v] = fmaf(av[u], bv[v], s[u][v]);
        }
        // scale + causal mask (tiles are aligned: only diagonal tile partial)
        const bool diag = (kt == it);
#pragma unroll
        for (int u = 0; u < 4; u++)
#pragma unroll
            for (int v = 0; v < 4; v++) {
                float val = s[u][v] * ATT_SCALE;
                if (diag && (j0 + v > i0 + u)) val = -1e30f;
                Ss[(i0 + u) * 65 + (j0 + v)] = val;
            }
        __syncthreads();

        // Online softmax: 4 threads per row (aligned lane groups of 4)
        {
            int r = tid >> 2;
            int q4 = tid & 3;
            float* row = &Ss[r * 65 + q4 * 16];
            float mx = -1e30f;
#pragma unroll
            for (int j = 0; j < 16; j++) mx = fmaxf(mx, row[j]);
            mx = fmaxf(mx, __shfl_xor_sync(0xffffffffu, mx, 1));
            mx = fmaxf(mx, __shfl_xor_sync(0xffffffffu, mx, 2));
            float m_old = m_s[r];
            float m_new = fmaxf(m_old, mx);
            float sum = 0.f;
#pragma unroll
            for (int j = 0; j < 16; j++) {
                float p = __expf(row[j] - m_new);
                row[j] = p;
                sum += p;
            }
            sum += __shfl_xor_sync(0xffffffffu, sum, 1);
            sum += __shfl_xor_sync(0xffffffffu, sum, 2);
            if (q4 == 0) {
                float rs = __expf(m_old - m_new);
                m_s[r] = m_new;
                l_s[r] = l_s[r] * rs + sum;
                rs_s[r] = rs;
            }
        }
        __syncthreads();

        // O = O*rescale + P @ V
        float rsc[4];
#pragma unroll
        for (int u = 0; u < 4; u++) rsc[u] = rs_s[i0 + u];
#pragma unroll
        for (int u = 0; u < 4; u++)
#pragma unroll
            for (int v = 0; v < 4; v++) o[u][v] *= rsc[u];
#pragma unroll 8
        for (int j = 0; j < 64; j++) {
            float4 b4 = *(const float4*)&Vs[j * 64 + h0];
            float bv[4] = {b4.x, b4.y, b4.z, b4.w};
            float av[4];
#pragma unroll
            for (int u = 0; u < 4; u++) av[u] = Ss[(i0 + u) * 65 + j];
#pragma unroll
            for (int u = 0; u < 4; u++)
#pragma unroll
                for (int v = 0; v < 4; v++) o[u][v] = fmaf(av[u], bv[v], o[u][v]);
        }
    }

    // Epilogue: normalize by l and write [B,T,H]
#pragma unroll
    for (int u = 0; u < 4; u++) {
        float inv = 1.f / l_s[i0 + u];
        int row = b * Tq + qm0 + i0 + u;
        float4 r4 = make_float4(o[u][0] * inv, o[u][1] * inv, o[u][2] * inv, o[u][3] * inv);
        *(float4*)&out[row * Hq + h0] = r4;
    }
}

// ---------------------------------------------------------------------------
extern "C" void kernel_launch(void* const* d_in, const int* in_sizes, int n_in,
                              void* d_out, int out_size) {
    const float* x = (const float*)d_in[0];
    const float* Wq = (const float*)d_in[1];
    const float* Wk = (const float*)d_in[2];
    const float* Wv = (const float*)d_in[3];
    float* out = (float*)d_out;

    proj_kernel<<<(Bq * Tq) / PJ_BM, 256>>>(x, Wq, Wk, Wv);

    static const size_t smem_bytes = SMEM_FLOATS * sizeof(float);
    cudaFuncSetAttribute(attn_kernel, cudaFuncAttributeMaxDynamicSharedMemorySize,
                         (int)smem_bytes);
    attn_kernel<<<dim3(Tq / AT_BM, Bq), 256, smem_bytes>>>(out);
}

// round 2
// speedup vs baseline: 2.1966x; 2.1966x over previous
#include <cuda_runtime.h>
#include <math.h>
#include <stdint.h>

#define Bq 4
#define Tq 4096
#define Cq 1024
#define Hq 64

// Scratch: q,k natural [B,T,H]; v transposed [B,H,T] (for conflict-free PV B-frags).
__device__ float g_q[Bq * Tq * Hq];
__device__ float g_k[Bq * Tq * Hq];
__device__ float g_vT[Bq * Hq * Tq];

__device__ __forceinline__ uint32_t f2tf(float f) {
    uint32_t r;
    asm("cvt.rna.tf32.f32 %0, %1;" : "=r"(r) : "f"(f));
    return r;
}

__device__ __forceinline__ void mma_tf32(float d[4], const uint32_t a[4],
                                         const uint32_t b[2]) {
    asm volatile(
        "mma.sync.aligned.m16n8k8.row.col.f32.tf32.tf32.f32 "
        "{%0,%1,%2,%3}, {%4,%5,%6,%7}, {%8,%9}, {%0,%1,%2,%3};\n"
        : "+f"(d[0]), "+f"(d[1]), "+f"(d[2]), "+f"(d[3])
        : "r"(a[0]), "r"(a[1]), "r"(a[2]), "r"(a[3]), "r"(b[0]), "r"(b[1]));
}

// ---------------------------------------------------------------------------
// Projection: [16384,1024] @ [1024,192] via tf32 mma.
// Block: 64 rows x 192 cols, 256 threads (8 warps: 2 in M x 4 in N).
// ---------------------------------------------------------------------------
#define PJ_BM 64
#define PJ_N 192
#define PJ_KC 32
#define XS_PAD 36
#define WS_PAD 200

__global__ __launch_bounds__(256) void proj_kernel(const float* __restrict__ x,
                                                   const float* __restrict__ Wq,
                                                   const float* __restrict__ Wk,
                                                   const float* __restrict__ Wv) {
    __shared__ uint32_t Xs[PJ_BM][XS_PAD];  // [m][k] tf32
    __shared__ uint32_t Ws[PJ_KC][WS_PAD];  // [k][n] tf32

    const int tid = threadIdx.x;
    const int lane = tid & 31;
    const int wid = tid >> 5;
    const int r = lane >> 2;
    const int c = lane & 3;
    const int mw = wid & 1;        // 2 warps in M
    const int nw = wid >> 1;       // 4 warps in N
    const int m_base = mw * 32;    // 2 m16 tiles
    const int n_base = nw * 48;    // 6 n8 tiles
    const int row0 = blockIdx.x * PJ_BM;

    float acc[2][6][4];
#pragma unroll
    for (int mt = 0; mt < 2; mt++)
#pragma unroll
        for (int nt = 0; nt < 6; nt++)
#pragma unroll
            for (int i = 0; i < 4; i++) acc[mt][nt][i] = 0.f;

    for (int kc = 0; kc < Cq; kc += PJ_KC) {
        // X tile (64x32) -> tf32
        for (int idx = tid; idx < PJ_BM * PJ_KC / 4; idx += 256) {
            int m = idx >> 3;
            int q = idx & 7;
            float4 v = *(const float4*)&x[(row0 + m) * Cq + kc + q * 4];
            uint4 tv = make_uint4(f2tf(v.x), f2tf(v.y), f2tf(v.z), f2tf(v.w));
            *(uint4*)&Xs[m][q * 4] = tv;
        }
        // W tile (32x192) -> tf32
        for (int idx = tid; idx < PJ_KC * PJ_N; idx += 256) {
            int k = idx / PJ_N;
            int n = idx % PJ_N;
            const float* W = (n < 64) ? Wq : ((n < 128) ? Wk : Wv);
            Ws[k][n] = f2tf(W[(kc + k) * Hq + (n & 63)]);
        }
        __syncthreads();

#pragma unroll
        for (int ks = 0; ks < 4; ks++) {
            const int k0 = ks * 8;
            uint32_t a[2][4];
#pragma unroll
            for (int mt = 0; mt < 2; mt++) {
                int mb = m_base + mt * 16;
                a[mt][0] = Xs[mb + r][k0 + c];
                a[mt][1] = Xs[mb + r + 8][k0 + c];
                a[mt][2] = Xs[mb + r][k0 + c + 4];
                a[mt][3] = Xs[mb + r + 8][k0 + c + 4];
            }
            uint32_t bf[6][2];
#pragma unroll
            for (int nt = 0; nt < 6; nt++) {
                int nb = n_base + nt * 8 + r;
                bf[nt][0] = Ws[k0 + c][nb];
                bf[nt][1] = Ws[k0 + 4 + c][nb];
            }
#pragma unroll
            for (int mt = 0; mt < 2; mt++)
#pragma unroll
                for (int nt = 0; nt < 6; nt++) mma_tf32(acc[mt][nt], a[mt], bf[nt]);
        }
        __syncthreads();
    }

    // Epilogue scatter
#pragma unroll
    for (int mt = 0; mt < 2; mt++) {
#pragma unroll
        for (int nt = 0; nt < 6; nt++) {
#pragma unroll
            for (int i = 0; i < 4; i++) {
                int row = row0 + m_base + mt * 16 + r + ((i >= 2) ? 8 : 0);
                int n = n_base + nt * 8 + 2 * c + (i & 1);
                float val = acc[mt][nt][i];
                if (n < 64) {
                    g_q[row * Hq + n] = val;
                } else if (n < 128) {
                    g_k[row * Hq + (n - 64)] = val;
                } else {
                    int b = row >> 12;
                    int t = row & 4095;
                    g_vT[(b * Hq + (n - 128)) * Tq + t] = val;
                }
            }
        }
    }
}

// ---------------------------------------------------------------------------
// Flash attention, tf32 mma. Block = 64 query rows x 64-key tiles streamed.
// 128 threads = 4 warps; warp w owns rows [w*16, w*16+16) -> warp-local softmax.
// ---------------------------------------------------------------------------
#define AT_PAD 68
#define ATT_SCALE 0.03125f  // 1/sqrt(1024)
#define AT_SMEM_WORDS (3 * 64 * AT_PAD)

__global__ __launch_bounds__(128) void attn_kernel(float* __restrict__ out) {
    extern __shared__ uint32_t sm[];
    uint32_t* Ks = sm;                  // [j][h] 64x68
    uint32_t* Vs = Ks + 64 * AT_PAD;    // [h][j] 64x68 (V transposed)
    uint32_t* Ps = Vs + 64 * AT_PAD;    // [m][j] 64x68

    const int tid = threadIdx.x;
    const int lane = tid & 31;
    const int w = tid >> 5;  // 0..3
    const int r = lane >> 2;
    const int c = lane & 3;
    const int b = blockIdx.y;
    const int it = (gridDim.x - 1) - blockIdx.x;  // big tiles first
    const int qm0 = it * 64;
    const int wr0 = qm0 + w * 16;  // this warp's first global query row (within batch)

    // Preload Q A-fragments (8 k-tiles) straight from gmem
    uint32_t qa[8][4];
    {
        const float* qb = g_q + (size_t)(b * Tq + wr0) * Hq;
#pragma unroll
        for (int k8 = 0; k8 < 8; k8++) {
            int k0 = k8 * 8;
            qa[k8][0] = f2tf(qb[r * Hq + k0 + c]);
            qa[k8][1] = f2tf(qb[(r + 8) * Hq + k0 + c]);
            qa[k8][2] = f2tf(qb[r * Hq + k0 + c + 4]);
            qa[k8][3] = f2tf(qb[(r + 8) * Hq + k0 + c + 4]);
        }
    }

    float m0 = -1e30f, m1 = -1e30f, l0 = 0.f, l1 = 0.f;
    float o[8][4];
#pragma unroll
    for (int ht = 0; ht < 8; ht++)
#pragma unroll
        for (int i = 0; i < 4; i++) o[ht][i] = 0.f;

    for (int kt = 0; kt <= it; kt++) {
        const int kn0 = kt * 64;
        __syncthreads();  // previous PV must be done before overwriting K/V
        // K tile -> Ks[j][h]
        for (int idx = tid; idx < 64 * 16; idx += 128) {
            int j = idx >> 4;
            int q = idx & 15;
            float4 v = *(const float4*)&g_k[(size_t)(b * Tq + kn0 + j) * Hq + q * 4];
            *(uint4*)&Ks[j * AT_PAD + q * 4] =
                make_uint4(f2tf(v.x), f2tf(v.y), f2tf(v.z), f2tf(v.w));
        }
        // V tile -> Vs[h][j]
        for (int idx = tid; idx < 64 * 16; idx += 128) {
            int h = idx >> 4;
            int q = idx & 15;
            float4 v = *(const float4*)&g_vT[(size_t)(b * Hq + h) * Tq + kn0 + q * 4];
            *(uint4*)&Vs[h * AT_PAD + q * 4] =
                make_uint4(f2tf(v.x), f2tf(v.y), f2tf(v.z), f2tf(v.w));
        }
        __syncthreads();

        // S = Q @ K^T  (warp: 16 rows x 64 cols)
        float s[8][4];
#pragma unroll
        for (int jt = 0; jt < 8; jt++)
#pragma unroll
            for (int i = 0; i < 4; i++) s[jt][i] = 0.f;
#pragma unroll
        for (int k8 = 0; k8 < 8; k8++) {
            const int k0 = k8 * 8;
#pragma unroll
            for (int jt = 0; jt < 8; jt++) {
                uint32_t bf[2];
                bf[0] = Ks[(jt * 8 + r) * AT_PAD + k0 + c];
                bf[1] = Ks[(jt * 8 + r) * AT_PAD + k0 + 4 + c];
                mma_tf32(s[jt], qa[k8], bf);
            }
        }

        // Scale + causal mask (only the diagonal tile is partial)
        const bool diag = (kt == it);
#pragma unroll
        for (int jt = 0; jt < 8; jt++) {
#pragma unroll
            for (int i = 0; i < 4; i++) {
                float v = s[jt][i] * ATT_SCALE;
                if (diag) {
                    int col = kn0 + jt * 8 + 2 * c + (i & 1);
                    int row = wr0 + r + ((i >= 2) ? 8 : 0);
                    if (col > row) v = -1e30f;
                }
                s[jt][i] = v;
            }
        }

        // Online softmax (rows r and r+8, spread over 4 lanes)
        float mx0 = -1e30f, mx1 = -1e30f;
#pragma unroll
        for (int jt = 0; jt < 8; jt++) {
            mx0 = fmaxf(mx0, fmaxf(s[jt][0], s[jt][1]));
            mx1 = fmaxf(mx1, fmaxf(s[jt][2], s[jt][3]));
        }
        mx0 = fmaxf(mx0, __shfl_xor_sync(0xffffffffu, mx0, 1));
        mx0 = fmaxf(mx0, __shfl_xor_sync(0xffffffffu, mx0, 2));
        mx1 = fmaxf(mx1, __shfl_xor_sync(0xffffffffu, mx1, 1));
        mx1 = fmaxf(mx1, __shfl_xor_sync(0xffffffffu, mx1, 2));
        float mn0 = fmaxf(m0, mx0), mn1 = fmaxf(m1, mx1);
        float sum0 = 0.f, sum1 = 0.f;
#pragma unroll
        for (int jt = 0; jt < 8; jt++) {
            s[jt][0] = __expf(s[jt][0] - mn0);
            s[jt][1] = __expf(s[jt][1] - mn0);
            s[jt][2] = __expf(s[jt][2] - mn1);
            s[jt][3] = __expf(s[jt][3] - mn1);
            sum0 += s[jt][0] + s[jt][1];
            sum1 += s[jt][2] + s[jt][3];
        }
        sum0 += __shfl_xor_sync(0xffffffffu, sum0, 1);
        sum0 += __shfl_xor_sync(0xffffffffu, sum0, 2);
        sum1 += __shfl_xor_sync(0xffffffffu, sum1, 1);
        sum1 += __shfl_xor_sync(0xffffffffu, sum1, 2);
        float rs0 = __expf(m0 - mn0), rs1 = __expf(m1 - mn1);
        m0 = mn0;
        m1 = mn1;
        l0 = l0 * rs0 + sum0;
        l1 = l1 * rs1 + sum1;

        // Store P (tf32) to warp-private rows of Ps
        {
            uint32_t* p0 = &Ps[(w * 16 + r) * AT_PAD];
            uint32_t* p1 = &Ps[(w * 16 + r + 8) * AT_PAD];
#pragma unroll
            for (int jt = 0; jt < 8; jt++) {
                p0[jt * 8 + 2 * c] = f2tf(s[jt][0]);
                p0[jt * 8 + 2 * c + 1] = f2tf(s[jt][1]);
                p1[jt * 8 + 2 * c] = f2tf(s[jt][2]);
                p1[jt * 8 + 2 * c + 1] = f2tf(s[jt][3]);
            }
        }
        __syncwarp();

        // Rescale O
#pragma unroll
        for (int ht = 0; ht < 8; ht++) {
            o[ht][0] *= rs0;
            o[ht][1] *= rs0;
            o[ht][2] *= rs1;
            o[ht][3] *= rs1;
        }

        // O += P @ V
#pragma unroll
        for (int j8 = 0; j8 < 8; j8++) {
            const int j0 = j8 * 8;
            uint32_t pa[4];
            pa[0] = Ps[(w * 16 + r) * AT_PAD + j0 + c];
            pa[1] = Ps[(w * 16 + r + 8) * AT_PAD + j0 + c];
            pa[2] = Ps[(w * 16 + r) * AT_PAD + j0 + 4 + c];
            pa[3] = Ps[(w * 16 + r + 8) * AT_PAD + j0 + 4 + c];
#pragma unroll
            for (int ht = 0; ht < 8; ht++) {
                uint32_t bf[2];
                bf[0] = Vs[(ht * 8 + r) * AT_PAD + j0 + c];
                bf[1] = Vs[(ht * 8 + r) * AT_PAD + j0 + 4 + c];
                mma_tf32(o[ht], pa, bf);
            }
        }
        __syncwarp();
    }

    // Epilogue: normalize and store
    float inv0 = 1.f / l0, inv1 = 1.f / l1;
    {
        float* ob0 = out + (size_t)(b * Tq + wr0 + r) * Hq;
        float* ob1 = out + (size_t)(b * Tq + wr0 + r + 8) * Hq;
#pragma unroll
        for (int ht = 0; ht < 8; ht++) {
            int col = ht * 8 + 2 * c;
            *(float2*)&ob0[col] = make_float2(o[ht][0] * inv0, o[ht][1] * inv0);
            *(float2*)&ob1[col] = make_float2(o[ht][2] * inv1, o[ht][3] * inv1);
        }
    }
}

// ---------------------------------------------------------------------------
extern "C" void kernel_launch(void* const* d_in, const int* in_sizes, int n_in,
                              void* d_out, int out_size) {
    const float* x = (const float*)d_in[0];
    const float* Wq = (const float*)d_in[1];
    const float* Wk = (const float*)d_in[2];
    const float* Wv = (const float*)d_in[3];
    float* out = (float*)d_out;

    proj_kernel<<<(Bq * Tq) / PJ_BM, 256>>>(x, Wq, Wk, Wv);

    const size_t smem_bytes = AT_SMEM_WORDS * sizeof(uint32_t);
    cudaFuncSetAttribute(attn_kernel, cudaFuncAttributeMaxDynamicSharedMemorySize,
                         (int)smem_bytes);
    attn_kernel<<<dim3(Tq / 64, Bq), 128, smem_bytes>>>(out);
}

// round 3
// speedup vs baseline: 2.8200x; 1.2838x over previous
#include <cuda_runtime.h>
#include <math.h>
#include <stdint.h>

#define Bq 4
#define Tq 4096
#define Cq 1024
#define Hq 64

// Scratch holds tf32-converted bits (round-to-nearest) produced by proj.
// q,k natural [B,T,H]; v transposed [B,H,T].
__device__ uint32_t g_q[Bq * Tq * Hq];
__device__ uint32_t g_k[Bq * Tq * Hq];
__device__ uint32_t g_vT[Bq * Hq * Tq];

__device__ __forceinline__ uint32_t f2tf(float f) {
    uint32_t r;
    asm("cvt.rna.tf32.f32 %0, %1;" : "=r"(r) : "f"(f));
    return r;
}

__device__ __forceinline__ float ex2(float x) {
    float y;
    asm("ex2.approx.ftz.f32 %0, %1;" : "=f"(y) : "f"(x));
    return y;
}

__device__ __forceinline__ void mma_tf32(float d[4], const uint32_t a[4],
                                         const uint32_t b[2]) {
    asm volatile(
        "mma.sync.aligned.m16n8k8.row.col.f32.tf32.tf32.f32 "
        "{%0,%1,%2,%3}, {%4,%5,%6,%7}, {%8,%9}, {%0,%1,%2,%3};\n"
        : "+f"(d[0]), "+f"(d[1]), "+f"(d[2]), "+f"(d[3])
        : "r"(a[0]), "r"(a[1]), "r"(a[2]), "r"(a[3]), "r"(b[0]), "r"(b[1]));
}

__device__ __forceinline__ void cp16(uint32_t saddr, const void* gptr) {
    asm volatile("cp.async.cg.shared.global [%0], [%1], 16;" ::"r"(saddr),
                 "l"(gptr));
}

// ---------------------------------------------------------------------------
// Projection: [16384,1024] @ [1024,192] via tf32 mma. Emits tf32 bits.
// ---------------------------------------------------------------------------
#define PJ_BM 64
#define PJ_N 192
#define PJ_KC 32
#define XS_PAD 36
#define WS_PAD 200

__global__ __launch_bounds__(256) void proj_kernel(const float* __restrict__ x,
                                                   const float* __restrict__ Wq,
                                                   const float* __restrict__ Wk,
                                                   const float* __restrict__ Wv) {
    __shared__ uint32_t Xs[PJ_BM][XS_PAD];
    __shared__ uint32_t Ws[PJ_KC][WS_PAD];

    const int tid = threadIdx.x;
    const int lane = tid & 31;
    const int wid = tid >> 5;
    const int r = lane >> 2;
    const int c = lane & 3;
    const int mw = wid & 1;
    const int nw = wid >> 1;
    const int m_base = mw * 32;
    const int n_base = nw * 48;
    const int row0 = blockIdx.x * PJ_BM;

    float acc[2][6][4];
#pragma unroll
    for (int mt = 0; mt < 2; mt++)
#pragma unroll
        for (int nt = 0; nt < 6; nt++)
#pragma unroll
            for (int i = 0; i < 4; i++) acc[mt][nt][i] = 0.f;

    for (int kc = 0; kc < Cq; kc += PJ_KC) {
        for (int idx = tid; idx < PJ_BM * PJ_KC / 4; idx += 256) {
            int m = idx >> 3;
            int q = idx & 7;
            float4 v = *(const float4*)&x[(row0 + m) * Cq + kc + q * 4];
            *(uint4*)&Xs[m][q * 4] =
                make_uint4(f2tf(v.x), f2tf(v.y), f2tf(v.z), f2tf(v.w));
        }
        for (int idx = tid; idx < PJ_KC * PJ_N; idx += 256) {
            int k = idx / PJ_N;
            int n = idx % PJ_N;
            const float* W = (n < 64) ? Wq : ((n < 128) ? Wk : Wv);
            Ws[k][n] = f2tf(W[(kc + k) * Hq + (n & 63)]);
        }
        __syncthreads();

#pragma unroll
        for (int ks = 0; ks < 4; ks++) {
            const int k0 = ks * 8;
            uint32_t a[2][4];
#pragma unroll
            for (int mt = 0; mt < 2; mt++) {
                int mb = m_base + mt * 16;
                a[mt][0] = Xs[mb + r][k0 + c];
                a[mt][1] = Xs[mb + r + 8][k0 + c];
                a[mt][2] = Xs[mb + r][k0 + c + 4];
                a[mt][3] = Xs[mb + r + 8][k0 + c + 4];
            }
            uint32_t bf[6][2];
#pragma unroll
            for (int nt = 0; nt < 6; nt++) {
                int nb = n_base + nt * 8 + r;
                bf[nt][0] = Ws[k0 + c][nb];
                bf[nt][1] = Ws[k0 + 4 + c][nb];
            }
#pragma unroll
            for (int mt = 0; mt < 2; mt++)
#pragma unroll
                for (int nt = 0; nt < 6; nt++) mma_tf32(acc[mt][nt], a[mt], bf[nt]);
        }
        __syncthreads();
    }

#pragma unroll
    for (int mt = 0; mt < 2; mt++) {
#pragma unroll
        for (int nt = 0; nt < 6; nt++) {
#pragma unroll
            for (int i = 0; i < 4; i++) {
                int row = row0 + m_base + mt * 16 + r + ((i >= 2) ? 8 : 0);
                int n = n_base + nt * 8 + 2 * c + (i & 1);
                uint32_t val = f2tf(acc[mt][nt][i]);
                if (n < 64) {
                    g_q[row * Hq + n] = val;
                } else if (n < 128) {
                    g_k[row * Hq + (n - 64)] = val;
                } else {
                    int b = row >> 12;
                    int t = row & 4095;
                    g_vT[(b * Hq + (n - 128)) * Tq + t] = val;
                }
            }
        }
    }
}

// ---------------------------------------------------------------------------
// Flash attention with intra-block 2-way key split.
// 256 threads = 8 warps: warp w -> key-group g=w>>2, row-group rg=w&3.
// Group g handles key tiles kt ≡ g (mod 2), own K/V/P smem + named barrier.
// End merge of the two online-softmax states via smem.
// ---------------------------------------------------------------------------
#define AT_PAD 68
// log2(e) / sqrt(1024)
#define SCALE2 0.04508422002f

// words: per group K(64*68)+V(64*68) = 8704, x2 = 17408; P 64*68 x2 = 8704
#define AT_SMEM_WORDS (2 * 2 * 64 * AT_PAD + 2 * 64 * AT_PAD)

__global__ __launch_bounds__(256, 2) void attn_kernel(float* __restrict__ out) {
    extern __shared__ uint32_t sm[];

    const int tid = threadIdx.x;
    const int lane = tid & 31;
    const int w = tid >> 5;
    const int g = w >> 2;        // key-split group
    const int rg = w & 3;        // row group
    const int gtid = tid & 127;  // thread id within group
    const int r = lane >> 2;
    const int c = lane & 3;
    const int b = blockIdx.y;
    const int it = (gridDim.x - 1) - blockIdx.x;
    const int qm0 = it * 64;
    const int wr0 = qm0 + rg * 16;

    uint32_t* Kg = sm + g * (2 * 64 * AT_PAD);
    uint32_t* Vg = Kg + 64 * AT_PAD;
    uint32_t* Pg = sm + 2 * (2 * 64 * AT_PAD) + g * (64 * AT_PAD);
    const int barid = g + 1;

    // Q A-fragments (tf32 bits already)
    uint32_t qa[8][4];
    {
        const uint32_t* qb = g_q + (size_t)(b * Tq + wr0) * Hq;
#pragma unroll
        for (int k8 = 0; k8 < 8; k8++) {
            int k0 = k8 * 8;
            qa[k8][0] = qb[r * Hq + k0 + c];
            qa[k8][1] = qb[(r + 8) * Hq + k0 + c];
            qa[k8][2] = qb[r * Hq + k0 + c + 4];
            qa[k8][3] = qb[(r + 8) * Hq + k0 + c + 4];
        }
    }

    float m0 = -1e30f, m1 = -1e30f, l0 = 0.f, l1 = 0.f;
    float o[8][4];
#pragma unroll
    for (int ht = 0; ht < 8; ht++)
#pragma unroll
        for (int i = 0; i < 4; i++) o[ht][i] = 0.f;

    for (int kt = g; kt <= it; kt += 2) {
        const int kn0 = kt * 64;
        // group-local: previous PV reads of Kg/Vg done
        asm volatile("bar.sync %0, %1;" ::"r"(barid), "r"(128) : "memory");
        // async K/V tile loads (raw tf32 bits)
        for (int idx = gtid; idx < 1024; idx += 128) {
            int j = idx >> 4;
            int q = idx & 15;
            cp16((uint32_t)__cvta_generic_to_shared(&Kg[j * AT_PAD + q * 4]),
                 &g_k[(size_t)(b * Tq + kn0 + j) * Hq + q * 4]);
        }
        for (int idx = gtid; idx < 1024; idx += 128) {
            int h = idx >> 4;
            int q = idx & 15;
            cp16((uint32_t)__cvta_generic_to_shared(&Vg[h * AT_PAD + q * 4]),
                 &g_vT[(size_t)(b * Hq + h) * Tq + kn0 + q * 4]);
        }
        asm volatile("cp.async.commit_group;" ::: "memory");
        asm volatile("cp.async.wait_group 0;" ::: "memory");
        asm volatile("bar.sync %0, %1;" ::"r"(barid), "r"(128) : "memory");

        // S = Q @ K^T
        float s[8][4];
#pragma unroll
        for (int jt = 0; jt < 8; jt++)
#pragma unroll
            for (int i = 0; i < 4; i++) s[jt][i] = 0.f;
#pragma unroll
        for (int k8 = 0; k8 < 8; k8++) {
            const int k0 = k8 * 8;
#pragma unroll
            for (int jt = 0; jt < 8; jt++) {
                uint32_t bf[2];
                bf[0] = Kg[(jt * 8 + r) * AT_PAD + k0 + c];
                bf[1] = Kg[(jt * 8 + r) * AT_PAD + k0 + 4 + c];
                mma_tf32(s[jt], qa[k8], bf);
            }
        }

        // scale (exp2 domain) + causal mask (diagonal tile only)
        const bool diag = (kt == it);
#pragma unroll
        for (int jt = 0; jt < 8; jt++) {
#pragma unroll
            for (int i = 0; i < 4; i++) {
                float v = s[jt][i] * SCALE2;
                if (diag) {
                    int col = jt * 8 + 2 * c + (i & 1);
                    int row = rg * 16 + r + ((i >= 2) ? 8 : 0);
                    if (col > row) v = -1e30f;
                }
                s[jt][i] = v;
            }
        }

        // online softmax (base-2)
        float mx0 = -1e30f, mx1 = -1e30f;
#pragma unroll
        for (int jt = 0; jt < 8; jt++) {
            mx0 = fmaxf(mx0, fmaxf(s[jt][0], s[jt][1]));
            mx1 = fmaxf(mx1, fmaxf(s[jt][2], s[jt][3]));
        }
        mx0 = fmaxf(mx0, __shfl_xor_sync(0xffffffffu, mx0, 1));
        mx0 = fmaxf(mx0, __shfl_xor_sync(0xffffffffu, mx0, 2));
        mx1 = fmaxf(mx1, __shfl_xor_sync(0xffffffffu, mx1, 1));
        mx1 = fmaxf(mx1, __shfl_xor_sync(0xffffffffu, mx1, 2));
        float mn0 = fmaxf(m0, mx0), mn1 = fmaxf(m1, mx1);
        float sum0 = 0.f, sum1 = 0.f;
#pragma unroll
        for (int jt = 0; jt < 8; jt++) {
            s[jt][0] = ex2(s[jt][0] - mn0);
            s[jt][1] = ex2(s[jt][1] - mn0);
            s[jt][2] = ex2(s[jt][2] - mn1);
            s[jt][3] = ex2(s[jt][3] - mn1);
            sum0 += s[jt][0] + s[jt][1];
            sum1 += s[jt][2] + s[jt][3];
        }
        sum0 += __shfl_xor_sync(0xffffffffu, sum0, 1);
        sum0 += __shfl_xor_sync(0xffffffffu, sum0, 2);
        sum1 += __shfl_xor_sync(0xffffffffu, sum1, 1);
        sum1 += __shfl_xor_sync(0xffffffffu, sum1, 2);
        float rs0 = ex2(m0 - mn0), rs1 = ex2(m1 - mn1);
        m0 = mn0;
        m1 = mn1;
        l0 = l0 * rs0 + sum0;
        l1 = l1 * rs1 + sum1;

        // P -> smem (warp-private rows)
        {
            uint32_t* p0 = &Pg[(rg * 16 + r) * AT_PAD];
            uint32_t* p1 = &Pg[(rg * 16 + r + 8) * AT_PAD];
#pragma unroll
            for (int jt = 0; jt < 8; jt++) {
                p0[jt * 8 + 2 * c] = f2tf(s[jt][0]);
                p0[jt * 8 + 2 * c + 1] = f2tf(s[jt][1]);
                p1[jt * 8 + 2 * c] = f2tf(s[jt][2]);
                p1[jt * 8 + 2 * c + 1] = f2tf(s[jt][3]);
            }
        }
        __syncwarp();

#pragma unroll
        for (int ht = 0; ht < 8; ht++) {
            o[ht][0] *= rs0;
            o[ht][1] *= rs0;
            o[ht][2] *= rs1;
            o[ht][3] *= rs1;
        }

        // O += P @ V
#pragma unroll
        for (int j8 = 0; j8 < 8; j8++) {
            const int j0 = j8 * 8;
            uint32_t pa[4];
            pa[0] = Pg[(rg * 16 + r) * AT_PAD + j0 + c];
            pa[1] = Pg[(rg * 16 + r + 8) * AT_PAD + j0 + c];
            pa[2] = Pg[(rg * 16 + r) * AT_PAD + j0 + 4 + c];
            pa[3] = Pg[(rg * 16 + r + 8) * AT_PAD + j0 + 4 + c];
#pragma unroll
            for (int ht = 0; ht < 8; ht++) {
                uint32_t bf[2];
                bf[0] = Vg[(ht * 8 + r) * AT_PAD + j0 + c];
                bf[1] = Vg[(ht * 8 + r) * AT_PAD + j0 + 4 + c];
                mma_tf32(o[ht], pa, bf);
            }
        }
        __syncwarp();
    }

    // ------- merge the two key-split states -------
    __syncthreads();
    float* oS = (float*)sm;                  // [4][32][32]
    float* mlS = (float*)(sm + 4 * 32 * 32); // [4][32][4]
    if (g == 1) {
        float* dst = &oS[(rg * 32 + lane) * 32];
#pragma unroll
        for (int ht = 0; ht < 8; ht++)
#pragma unroll
            for (int i = 0; i < 4; i++) dst[ht * 4 + i] = o[ht][i];
        float* ml = &mlS[(rg * 32 + lane) * 4];
        ml[0] = m0;
        ml[1] = l0;
        ml[2] = m1;
        ml[3] = l1;
    }
    __syncthreads();
    if (g == 0) {
        const float* ml = &mlS[(rg * 32 + lane) * 4];
        float pm0 = ml[0], pl0 = ml[1], pm1 = ml[2], pl1 = ml[3];
        float M0 = fmaxf(m0, pm0), M1 = fmaxf(m1, pm1);
        float a0 = ex2(m0 - M0), b0v = ex2(pm0 - M0);
        float a1 = ex2(m1 - M1), b1v = ex2(pm1 - M1);
        float inv0 = 1.f / (l0 * a0 + pl0 * b0v);
        float inv1 = 1.f / (l1 * a1 + pl1 * b1v);
        const float* po = &oS[(rg * 32 + lane) * 32];
        float* ob0 = out + (size_t)(b * Tq + wr0 + r) * Hq;
        float* ob1 = out + (size_t)(b * Tq + wr0 + r + 8) * Hq;
#pragma unroll
        for (int ht = 0; ht < 8; ht++) {
            int col = ht * 8 + 2 * c;
            float v0 = (o[ht][0] * a0 + po[ht * 4 + 0] * b0v) * inv0;
            float v1 = (o[ht][1] * a0 + po[ht * 4 + 1] * b0v) * inv0;
            float v2 = (o[ht][2] * a1 + po[ht * 4 + 2] * b1v) * inv1;
            float v3 = (o[ht][3] * a1 + po[ht * 4 + 3] * b1v) * inv1;
            *(float2*)&ob0[col] = make_float2(v0, v1);
            *(float2*)&ob1[col] = make_float2(v2, v3);
        }
    }
}

// ---------------------------------------------------------------------------
extern "C" void kernel_launch(void* const* d_in, const int* in_sizes, int n_in,
                              void* d_out, int out_size) {
    const float* x = (const float*)d_in[0];
    const float* Wq = (const float*)d_in[1];
    const float* Wk = (const float*)d_in[2];
    const float* Wv = (const float*)d_in[3];
    float* out = (float*)d_out;

    proj_kernel<<<(Bq * Tq) / PJ_BM, 256>>>(x, Wq, Wk, Wv);

    const size_t smem_bytes = AT_SMEM_WORDS * sizeof(uint32_t);
    cudaFuncSetAttribute(attn_kernel, cudaFuncAttributeMaxDynamicSharedMemorySize,
                         (int)smem_bytes);
    attn_kernel<<<dim3(Tq / 64, Bq), 256, smem_bytes>>>(out);
}

// round 5
// speedup vs baseline: 4.0551x; 1.4380x over previous
#include <cuda_runtime.h>
#include <math.h>
#include <stdint.h>

#define Bq 4
#define Tq 4096
#define Cq 1024
#define Hq 64

// Scratch (tf32 bits): q,k natural [B,T,H]; v transposed [B,H,T]; W pre-converted [1024][192].
__device__ uint32_t g_q[Bq * Tq * Hq];
__device__ uint32_t g_k[Bq * Tq * Hq];
__device__ uint32_t g_vT[Bq * Hq * Tq];
__device__ uint32_t g_w[Cq * 192];

__device__ __forceinline__ uint32_t f2tf(float f) {
    uint32_t r;
    asm("cvt.rna.tf32.f32 %0, %1;" : "=r"(r) : "f"(f));
    return r;
}

__device__ __forceinline__ float ex2(float x) {
    float y;
    asm("ex2.approx.ftz.f32 %0, %1;" : "=f"(y) : "f"(x));
    return y;
}

__device__ __forceinline__ void mma_tf32(float d[4], const uint32_t a[4],
                                         const uint32_t b[2]) {
    asm volatile(
        "mma.sync.aligned.m16n8k8.row.col.f32.tf32.tf32.f32 "
        "{%0,%1,%2,%3}, {%4,%5,%6,%7}, {%8,%9}, {%0,%1,%2,%3};\n"
        : "+f"(d[0]), "+f"(d[1]), "+f"(d[2]), "+f"(d[3])
        : "r"(a[0]), "r"(a[1]), "r"(a[2]), "r"(a[3]), "r"(b[0]), "r"(b[1]));
}

__device__ __forceinline__ void cp16(uint32_t saddr, const void* gptr) {
    asm volatile("cp.async.cg.shared.global [%0], [%1], 16;" ::"r"(saddr),
                 "l"(gptr));
}

// ---------------------------------------------------------------------------
// W pre-conversion: [1024][64]x3 fp32 -> g_w[1024][192] tf32 bits
// ---------------------------------------------------------------------------
__global__ __launch_bounds__(256) void wcvt_kernel(const float* __restrict__ Wq,
                                                   const float* __restrict__ Wk,
                                                   const float* __restrict__ Wv) {
    int i = blockIdx.x * 256 + threadIdx.x;  // 0..196607
    int k = i / 192;
    int n = i % 192;
    const float* W = (n < 64) ? Wq : ((n < 128) ? Wk : Wv);
    g_w[i] = f2tf(W[k * Hq + (n & 63)]);
}

// ---------------------------------------------------------------------------
// Projection: [16384,1024] @ [1024,192], tf32 mma, 2-stage cp.async pipeline.
// Block: 64 rows x 192 cols, 256 threads (8 warps: 2M x 4N).
// ---------------------------------------------------------------------------
#define PJ_BM 64
#define PJ_N 192
#define PJ_KC 32
#define XP 36    // x smem pitch (words)
#define WP 200   // W smem pitch (words)
#define PJ_STAGE_WORDS (PJ_BM * XP + PJ_KC * WP)  // 2304 + 6400 = 8704
#define PJ_SMEM_WORDS (2 * PJ_STAGE_WORDS)

__device__ __forceinline__ void pj_issue(uint32_t* stage_base, const float* x,
                                         int row0, int kc, int tid) {
    uint32_t* Xs = stage_base;
    uint32_t* Ws = stage_base + PJ_BM * XP;
    // x tile 64x32 fp32: 512 float4 over 256 threads
#pragma unroll
    for (int rep = 0; rep < 2; rep++) {
        int idx = tid + rep * 256;
        int m = idx >> 3;
        int q = idx & 7;
        cp16((uint32_t)__cvta_generic_to_shared(&Xs[m * XP + q * 4]),
             &x[(size_t)(row0 + m) * Cq + kc + q * 4]);
    }
    // W tile 32x192 tf32: 1536 uint4 over 256 threads
#pragma unroll
    for (int rep = 0; rep < 6; rep++) {
        int idx = tid + rep * 256;
        int k = idx / 48;
        int q = idx % 48;
        cp16((uint32_t)__cvta_generic_to_shared(&Ws[k * WP + q * 4]),
             &g_w[(size_t)(kc + k) * 192 + q * 4]);
    }
    asm volatile("cp.async.commit_group;" ::: "memory");
}

__global__ __launch_bounds__(256) void proj_kernel(const float* __restrict__ x) {
    extern __shared__ uint32_t psm[];

    const int tid = threadIdx.x;
    const int lane = tid & 31;
    const int wid = tid >> 5;
    const int r = lane >> 2;
    const int c = lane & 3;
    const int m_base = (wid & 1) * 32;
    const int n_base = (wid >> 1) * 48;
    const int row0 = blockIdx.x * PJ_BM;

    float acc[2][6][4];
#pragma unroll
    for (int mt = 0; mt < 2; mt++)
#pragma unroll
        for (int nt = 0; nt < 6; nt++)
#pragma unroll
            for (int i = 0; i < 4; i++) acc[mt][nt][i] = 0.f;

    const int NCHUNK = Cq / PJ_KC;  // 32
    pj_issue(psm, x, row0, 0, tid);

    for (int ci = 0; ci < NCHUNK; ci++) {
        if (ci + 1 < NCHUNK)
            pj_issue(psm + ((ci + 1) & 1) * PJ_STAGE_WORDS, x, row0,
                     (ci + 1) * PJ_KC, tid);
        if (ci + 1 < NCHUNK)
            asm volatile("cp.async.wait_group 1;" ::: "memory");
        else
            asm volatile("cp.async.wait_group 0;" ::: "memory");
        __syncthreads();

        uint32_t* Xs = psm + (ci & 1) * PJ_STAGE_WORDS;
        uint32_t* Ws = Xs + PJ_BM * XP;
        const float* Xf = (const float*)Xs;

#pragma unroll
        for (int ks = 0; ks < 4; ks++) {
            const int k0 = ks * 8;
            uint32_t a[2][4];
#pragma unroll
            for (int mt = 0; mt < 2; mt++) {
                int mb = m_base + mt * 16;
                a[mt][0] = f2tf(Xf[(mb + r) * XP + k0 + c]);
                a[mt][1] = f2tf(Xf[(mb + r + 8) * XP + k0 + c]);
                a[mt][2] = f2tf(Xf[(mb + r) * XP + k0 + c + 4]);
                a[mt][3] = f2tf(Xf[(mb + r + 8) * XP + k0 + c + 4]);
            }
            uint32_t bf[6][2];
#pragma unroll
            for (int nt = 0; nt < 6; nt++) {
                int nb = n_base + nt * 8 + r;
                bf[nt][0] = Ws[(k0 + c) * WP + nb];
                bf[nt][1] = Ws[(k0 + 4 + c) * WP + nb];
            }
#pragma unroll
            for (int mt = 0; mt < 2; mt++)
#pragma unroll
                for (int nt = 0; nt < 6; nt++) mma_tf32(acc[mt][nt], a[mt], bf[nt]);
        }
        __syncthreads();
    }

    // Epilogue scatter (tf32 bits)
#pragma unroll
    for (int mt = 0; mt < 2; mt++) {
#pragma unroll
        for (int nt = 0; nt < 6; nt++) {
#pragma unroll
            for (int i = 0; i < 4; i++) {
                int row = row0 + m_base + mt * 16 + r + ((i >= 2) ? 8 : 0);
                int n = n_base + nt * 8 + 2 * c + (i & 1);
                uint32_t val = f2tf(acc[mt][nt][i]);
                if (n < 64) {
                    g_q[row * Hq + n] = val;
                } else if (n < 128) {
                    g_k[row * Hq + (n - 64)] = val;
                } else {
                    int b = row >> 12;
                    int t = row & 4095;
                    g_vT[(b * Hq + (n - 128)) * Tq + t] = val;
                }
            }
        }
    }
}

// ---------------------------------------------------------------------------
// Flash attention with intra-block 2-way key split + K/V split-wait overlap.
// ---------------------------------------------------------------------------
#define AT_PAD 68
#define SCALE2 0.04508422002f  // log2(e)/sqrt(1024)
#define AT_SMEM_WORDS (2 * 2 * 64 * AT_PAD + 2 * 64 * AT_PAD)

__global__ __launch_bounds__(256, 2) void attn_kernel(float* __restrict__ out) {
    extern __shared__ uint32_t sm[];

    const int tid = threadIdx.x;
    const int lane = tid & 31;
    const int w = tid >> 5;
    const int g = w >> 2;
    const int rg = w & 3;
    const int gtid = tid & 127;
    const int r = lane >> 2;
    const int c = lane & 3;
    const int b = blockIdx.y;
    const int it = (gridDim.x - 1) - blockIdx.x;
    const int qm0 = it * 64;
    const int wr0 = qm0 + rg * 16;

    uint32_t* Kg = sm + g * (2 * 64 * AT_PAD);
    uint32_t* Vg = Kg + 64 * AT_PAD;
    uint32_t* Pg = sm + 2 * (2 * 64 * AT_PAD) + g * (64 * AT_PAD);
    const int barid = g + 1;

    uint32_t qa[8][4];
    {
        const uint32_t* qb = g_q + (size_t)(b * Tq + wr0) * Hq;
#pragma unroll
        for (int k8 = 0; k8 < 8; k8++) {
            int k0 = k8 * 8;
            qa[k8][0] = qb[r * Hq + k0 + c];
            qa[k8][1] = qb[(r + 8) * Hq + k0 + c];
            qa[k8][2] = qb[r * Hq + k0 + c + 4];
            qa[k8][3] = qb[(r + 8) * Hq + k0 + c + 4];
        }
    }

    float m0 = -1e30f, m1 = -1e30f, l0 = 0.f, l1 = 0.f;
    float o[8][4];
#pragma unroll
    for (int ht = 0; ht < 8; ht++)
#pragma unroll
        for (int i = 0; i < 4; i++) o[ht][i] = 0.f;

    for (int kt = g; kt <= it; kt += 2) {
        const int kn0 = kt * 64;
        asm volatile("bar.sync %0, %1;" ::"r"(barid), "r"(128) : "memory");
        // K tile group
        for (int idx = gtid; idx < 1024; idx += 128) {
            int j = idx >> 4;
            int q = idx & 15;
            cp16((uint32_t)__cvta_generic_to_shared(&Kg[j * AT_PAD + q * 4]),
                 &g_k[(size_t)(b * Tq + kn0 + j) * Hq + q * 4]);
        }
        asm volatile("cp.async.commit_group;" ::: "memory");
        // V tile group
        for (int idx = gtid; idx < 1024; idx += 128) {
            int h = idx >> 4;
            int q = idx & 15;
            cp16((uint32_t)__cvta_generic_to_shared(&Vg[h * AT_PAD + q * 4]),
                 &g_vT[(size_t)(b * Hq + h) * Tq + kn0 + q * 4]);
        }
        asm volatile("cp.async.commit_group;" ::: "memory");
        // wait K only; V continues in flight under S+softmax
        asm volatile("cp.async.wait_group 1;" ::: "memory");
        asm volatile("bar.sync %0, %1;" ::"r"(barid), "r"(128) : "memory");

        // S = Q @ K^T
        float s[8][4];
#pragma unroll
        for (int jt = 0; jt < 8; jt++)
#pragma unroll
            for (int i = 0; i < 4; i++) s[jt][i] = 0.f;
#pragma unroll
        for (int k8 = 0; k8 < 8; k8++) {
            const int k0 = k8 * 8;
#pragma unroll
            for (int jt = 0; jt < 8; jt++) {
                uint32_t bf[2];
                bf[0] = Kg[(jt * 8 + r) * AT_PAD + k0 + c];
                bf[1] = Kg[(jt * 8 + r) * AT_PAD + k0 + 4 + c];
                mma_tf32(s[jt], qa[k8], bf);
            }
        }

        const bool diag = (kt == it);
#pragma unroll
        for (int jt = 0; jt < 8; jt++) {
#pragma unroll
            for (int i = 0; i < 4; i++) {
                float v = s[jt][i] * SCALE2;
                if (diag) {
                    int col = jt * 8 + 2 * c + (i & 1);
                    int row = rg * 16 + r + ((i >= 2) ? 8 : 0);
                    if (col > row) v = -1e30f;
                }
                s[jt][i] = v;
            }
        }

        // online softmax (base-2)
        float mx0 = -1e30f, mx1 = -1e30f;
#pragma unroll
        for (int jt = 0; jt < 8; jt++) {
            mx0 = fmaxf(mx0, fmaxf(s[jt][0], s[jt][1]));
            mx1 = fmaxf(mx1, fmaxf(s[jt][2], s[jt][3]));
        }
        mx0 = fmaxf(mx0, __shfl_xor_sync(0xffffffffu, mx0, 1));
        mx0 = fmaxf(mx0, __shfl_xor_sync(0xffffffffu, mx0, 2));
        mx1 = fmaxf(mx1, __shfl_xor_sync(0xffffffffu, mx1, 1));
        mx1 = fmaxf(mx1, __shfl_xor_sync(0xffffffffu, mx1, 2));
        float mn0 = fmaxf(m0, mx0), mn1 = fmaxf(m1, mx1);
        float sum0 = 0.f, sum1 = 0.f;
#pragma unroll
        for (int jt = 0; jt < 8; jt++) {
            s[jt][0] = ex2(s[jt][0] - mn0);
            s[jt][1] = ex2(s[jt][1] - mn0);
            s[jt][2] = ex2(s[jt][2] - mn1);
            s[jt][3] = ex2(s[jt][3] - mn1);
            sum0 += s[jt][0] + s[jt][1];
            sum1 += s[jt][2] + s[jt][3];
        }
        sum0 += __shfl_xor_sync(0xffffffffu, sum0, 1);
        sum0 += __shfl_xor_sync(0xffffffffu, sum0, 2);
        sum1 += __shfl_xor_sync(0xffffffffu, sum1, 1);
        sum1 += __shfl_xor_sync(0xffffffffu, sum1, 2);
        float rs0 = ex2(m0 - mn0), rs1 = ex2(m1 - mn1);
        m0 = mn0;
        m1 = mn1;
        l0 = l0 * rs0 + sum0;
        l1 = l1 * rs1 + sum1;

        // P -> smem (warp-private rows)
        {
            uint32_t* p0 = &Pg[(rg * 16 + r) * AT_PAD];
            uint32_t* p1 = &Pg[(rg * 16 + r + 8) * AT_PAD];
#pragma unroll
            for (int jt = 0; jt < 8; jt++) {
                p0[jt * 8 + 2 * c] = f2tf(s[jt][0]);
                p0[jt * 8 + 2 * c + 1] = f2tf(s[jt][1]);
                p1[jt * 8 + 2 * c] = f2tf(s[jt][2]);
                p1[jt * 8 + 2 * c + 1] = f2tf(s[jt][3]);
            }
        }
        __syncwarp();

#pragma unroll
        for (int ht = 0; ht < 8; ht++) {
            o[ht][0] *= rs0;
            o[ht][1] *= rs0;
            o[ht][2] *= rs1;
            o[ht][3] *= rs1;
        }

        // V must be resident now
        asm volatile("cp.async.wait_group 0;" ::: "memory");
        asm volatile("bar.sync %0, %1;" ::"r"(barid), "r"(128) : "memory");

        // O += P @ V
#pragma unroll
        for (int j8 = 0; j8 < 8; j8++) {
            const int j0 = j8 * 8;
            uint32_t pa[4];
            pa[0] = Pg[(rg * 16 + r) * AT_PAD + j0 + c];
            pa[1] = Pg[(rg * 16 + r + 8) * AT_PAD + j0 + c];
            pa[2] = Pg[(rg * 16 + r) * AT_PAD + j0 + 4 + c];
            pa[3] = Pg[(rg * 16 + r + 8) * AT_PAD + j0 + 4 + c];
#pragma unroll
            for (int ht = 0; ht < 8; ht++) {
                uint32_t bf[2];
                bf[0] = Vg[(ht * 8 + r) * AT_PAD + j0 + c];
                bf[1] = Vg[(ht * 8 + r) * AT_PAD + j0 + 4 + c];
                mma_tf32(o[ht], pa, bf);
            }
        }
        __syncwarp();
    }

    // ------- merge the two key-split states -------
    __syncthreads();
    float* oS = (float*)sm;
    float* mlS = (float*)(sm + 4 * 32 * 32);
    if (g == 1) {
        float* dst = &oS[(rg * 32 + lane) * 32];
#pragma unroll
        for (int ht = 0; ht < 8; ht++)
#pragma unroll
            for (int i = 0; i < 4; i++) dst[ht * 4 + i] = o[ht][i];
        float* ml = &mlS[(rg * 32 + lane) * 4];
        ml[0] = m0;
        ml[1] = l0;
        ml[2] = m1;
        ml[3] = l1;
    }
    __syncthreads();
    if (g == 0) {
        const float* ml = &mlS[(rg * 32 + lane) * 4];
        float pm0 = ml[0], pl0 = ml[1], pm1 = ml[2], pl1 = ml[3];
        float M0 = fmaxf(m0, pm0), M1 = fmaxf(m1, pm1);
        float a0 = ex2(m0 - M0), b0v = ex2(pm0 - M0);
        float a1 = ex2(m1 - M1), b1v = ex2(pm1 - M1);
        float inv0 = 1.f / (l0 * a0 + pl0 * b0v);
        float inv1 = 1.f / (l1 * a1 + pl1 * b1v);
        const float* po = &oS[(rg * 32 + lane) * 32];
        float* ob0 = out + (size_t)(b * Tq + wr0 + r) * Hq;
        float* ob1 = out + (size_t)(b * Tq + wr0 + r + 8) * Hq;
#pragma unroll
        for (int ht = 0; ht < 8; ht++) {
            int col = ht * 8 + 2 * c;
            float v0 = (o[ht][0] * a0 + po[ht * 4 + 0] * b0v) * inv0;
            float v1 = (o[ht][1] * a0 + po[ht * 4 + 1] * b0v) * inv0;
            float v2 = (o[ht][2] * a1 + po[ht * 4 + 2] * b1v) * inv1;
            float v3 = (o[ht][3] * a1 + po[ht * 4 + 3] * b1v) * inv1;
            *(float2*)&ob0[col] = make_float2(v0, v1);
            *(float2*)&ob1[col] = make_float2(v2, v3);
        }
    }
}

// ---------------------------------------------------------------------------
extern "C" void kernel_launch(void* const* d_in, const int* in_sizes, int n_in,
                              void* d_out, int out_size) {
    const float* x = (const float*)d_in[0];
    const float* Wq = (const float*)d_in[1];
    const float* Wk = (const float*)d_in[2];
    const float* Wv = (const float*)d_in[3];
    float* out = (float*)d_out;

    wcvt_kernel<<<(Cq * 192) / 256, 256>>>(Wq, Wk, Wv);

    const size_t pj_smem = PJ_SMEM_WORDS * sizeof(uint32_t);
    cudaFuncSetAttribute(proj_kernel, cudaFuncAttributeMaxDynamicSharedMemorySize,
                         (int)pj_smem);
    proj_kernel<<<(Bq * Tq) / PJ_BM, 256, pj_smem>>>(x);

    const size_t at_smem = AT_SMEM_WORDS * sizeof(uint32_t);
    cudaFuncSetAttribute(attn_kernel, cudaFuncAttributeMaxDynamicSharedMemorySize,
                         (int)at_smem);
    attn_kernel<<<dim3(Tq / 64, Bq), 256, at_smem>>>(out);
}